// round 17
// baseline (speedup 1.0000x reference)
#include <cuda_runtime.h>
#include <cuda_bf16.h>
#include <stdint.h>
#include <math.h>

#define BATCH 2048
#define NTOK 98
#define DIM 128
#define HEADS 4
#define NWIN 256
#define NN (NTOK * NTOK)   // 9604
#define MTOT (BATCH * NTOK)  // 200704

// Scratch (device globals)
__device__ uint32_t g_att[(size_t)MTOT * 128];              // packed attn out
__device__ uint32_t g_sbm[(size_t)NWIN * HEADS * 13 * 512]; // bias+mask, C-frag layout
__device__ uint4 g_wfrag[16384];                            // W in MMA-fragment layout
__device__ float g_qkvb[384];                               // qkv bias (Q slice pre-scaled)
__device__ uint4 g_xfrag[(size_t)BATCH * 7 * 8 * 64];       // x in A-fragment image (117 MB)

#define LOG2E 1.4426950408889634f
#define QSCALE (0.17677669529663687f * LOG2E)

// ===========================================================================
__device__ __forceinline__ uint32_t smem_u32(const void* p) {
    uint32_t a;
    asm("{ .reg .u64 t; cvta.to.shared.u64 t, %1; cvt.u32.u64 %0, t; }" : "=r"(a) : "l"(p));
    return a;
}
__device__ __forceinline__ void ldsm_x4(uint32_t* r, uint32_t addr) {
    asm volatile("ldmatrix.sync.aligned.m8n8.x4.shared.b16 {%0,%1,%2,%3}, [%4];"
                 : "=r"(r[0]), "=r"(r[1]), "=r"(r[2]), "=r"(r[3]) : "r"(addr));
}
__device__ __forceinline__ void ldsm_x2(uint32_t* r, uint32_t addr) {
    asm volatile("ldmatrix.sync.aligned.m8n8.x2.shared.b16 {%0,%1}, [%2];"
                 : "=r"(r[0]), "=r"(r[1]) : "r"(addr));
}
__device__ __forceinline__ void ldsm_x4t(uint32_t* r, uint32_t addr) {
    asm volatile("ldmatrix.sync.aligned.m8n8.x4.trans.shared.b16 {%0,%1,%2,%3}, [%4];"
                 : "=r"(r[0]), "=r"(r[1]), "=r"(r[2]), "=r"(r[3]) : "r"(addr));
}
__device__ __forceinline__ void mma_bf16(float* d, const uint32_t* a, const uint32_t* b) {
    asm volatile("mma.sync.aligned.m16n8k16.row.col.f32.bf16.bf16.f32 "
                 "{%0,%1,%2,%3}, {%4,%5,%6,%7}, {%8,%9}, {%0,%1,%2,%3};"
                 : "+f"(d[0]), "+f"(d[1]), "+f"(d[2]), "+f"(d[3])
                 : "r"(a[0]), "r"(a[1]), "r"(a[2]), "r"(a[3]), "r"(b[0]), "r"(b[1]));
}
__device__ __forceinline__ float ex2f(float x) {
    float y;
    asm("ex2.approx.ftz.f32 %0, %1;" : "=f"(y) : "f"(x));
    return y;
}
__device__ __forceinline__ uint32_t packbf(float a, float b) {
    __nv_bfloat162 t = __float22bfloat162_rn(make_float2(a, b));
    return *(uint32_t*)&t;
}
__device__ __forceinline__ float lopart(float v) {
    return v - __bfloat162float(__float2bfloat16(v));
}
// packed element: {hi16 (trunc) | lo16 (rn residual)}
__device__ __forceinline__ uint32_t pack_e(float v) {
    uint32_t hb = __float_as_uint(v) & 0xFFFF0000u;
    float l = v - __uint_as_float(hb);
    __nv_bfloat16 lb = __float2bfloat16(l);
    return hb | (uint32_t)(*(uint16_t*)&lb);
}
#define HIPAIR(a, b) __byte_perm((a), (b), 0x7632)
#define LOPAIR(a, b) __byte_perm((a), (b), 0x5410)
// truncation split of a float pair into hi (PRMT) and lo (residual)
__device__ __forceinline__ void tsplit2(float v0, float v1, uint32_t& hi, uint32_t& lo) {
    uint32_t b0 = __float_as_uint(v0), b1 = __float_as_uint(v1);
    hi = __byte_perm(b0, b1, 0x7632);
    float h0 = __uint_as_float(b0 & 0xFFFF0000u);
    float h1 = __uint_as_float(b1 & 0xFFFF0000u);
    lo = packbf(v0 - h0, v1 - h1);
}
__device__ __forceinline__ void split4(float4 v, uint2& hi, uint2& lo) {
    __nv_bfloat16 hx = __float2bfloat16(v.x), hy = __float2bfloat16(v.y);
    __nv_bfloat16 hz = __float2bfloat16(v.z), hw = __float2bfloat16(v.w);
    __nv_bfloat162 h0 = __halves2bfloat162(hx, hy), h1 = __halves2bfloat162(hz, hw);
    hi.x = *(uint32_t*)&h0; hi.y = *(uint32_t*)&h1;
    lo.x = packbf(v.x - __bfloat162float(hx), v.y - __bfloat162float(hy));
    lo.y = packbf(v.z - __bfloat162float(hz), v.w - __bfloat162float(hw));
}
// swizzled smem address: 256B-pitch rows, XOR 16B-chunk by row&7
__device__ __forceinline__ uint32_t swz(uint32_t r, uint32_t cb) {
    return (r << 8) + (cb ^ ((r & 7) << 4));
}

// ===========================================================================
// prep kernels
// ===========================================================================
__global__ void build_sbm_kernel(const float* __restrict__ table,
                                 const int* __restrict__ rel,
                                 const float* __restrict__ mask) {
    int rem = blockIdx.x * 256 + threadIdx.x;   // 0..6655 (13*512)
    int wh = blockIdx.y;
    if (rem >= 13 * 512) return;
    int nt = rem >> 9;
    int sub = rem & 511;
    int row = sub >> 2;
    int l4 = sub & 3;
    int w = wh >> 2, h = wh & 3;
    int col0 = nt * 8 + l4 * 2;
    float v0 = -1e30f, v1 = -1e30f;
    if (row < NTOK) {
        const float* mrow = mask + (size_t)w * NN + row * NTOK;
        const int* rrow = rel + row * NTOK;
        if (col0 < NTOK)
            v0 = (table[rrow[col0] * HEADS + h] + mrow[col0]) * LOG2E;
        if (col0 + 1 < NTOK)
            v1 = (table[rrow[col0 + 1] * HEADS + h] + mrow[col0 + 1]) * LOG2E;
    }
    g_sbm[((size_t)wh * 13 + nt) * 512 + sub] = packbf(v0, v1);
}

// W pre-split into MMA B-fragment layout; Q slice (tile 0) pre-scaled.
__global__ void split_w_kernel(const float* __restrict__ qkv_w,
                               const float* __restrict__ proj_w,
                               const float* __restrict__ qkv_b) {
    int idx = blockIdx.x * 256 + threadIdx.x;   // 16384
    if (idx < 384)
        g_qkvb[idx] = qkv_b[idx] * ((idx < 128) ? QSCALE : 1.0f);
    int tile = idx >> 12;
    int rem = idx & 4095;
    int lane = rem & 31;
    int nblk = (rem >> 5) & 15;
    int kc = rem >> 9;
    int n = nblk * 8 + (lane >> 2);
    int k0 = kc * 16 + (lane & 3) * 2;
    const float* W = (tile < 3) ? qkv_w + (size_t)(tile * 128 + n) * 128
                                : proj_w + (size_t)n * 128;
    float2 a = *(const float2*)(W + k0);
    float2 b = *(const float2*)(W + k0 + 8);
    float s = (tile == 0) ? QSCALE : 1.0f;
    a.x *= s; a.y *= s; b.x *= s; b.y *= s;
    uint4 o;
    {
        __nv_bfloat162 h = __halves2bfloat162(__float2bfloat16(a.x), __float2bfloat16(a.y));
        o.x = *(uint32_t*)&h;
        __nv_bfloat162 h2 = __halves2bfloat162(__float2bfloat16(b.x), __float2bfloat16(b.y));
        o.y = *(uint32_t*)&h2;
    }
    o.z = packbf(lopart(a.x), lopart(a.y));
    o.w = packbf(lopart(b.x), lopart(b.y));
    g_wfrag[idx] = o;
}

// x -> A-fragment image, window-padded (7 x 16-row blocks per window).
// Entry: blk = (w*7+mblk)*8+kc; hi at blk*64+lane, lo at blk*64+32+lane.
__global__ void build_xfrag(const float* __restrict__ x) {
    int gidx = blockIdx.x * 256 + threadIdx.x;   // 3,670,016
    if (gidx >= BATCH * 7 * 8 * 32) return;
    int lane = gidx & 31;
    int kc = (gidx >> 5) & 7;
    int blkw = gidx >> 8;            // w*7 + mblk
    int w = blkw / 7;
    int mblk = blkw - w * 7;
    int rq = lane >> 2;
    int cq = (lane & 3) * 2;
    int k0 = kc * 16 + cq;
    int r0 = mblk * 16 + rq;         // local rows
    int r1 = r0 + 8;
    const float* xw = x + (size_t)w * NTOK * 128;
    float2 p0 = (r0 < NTOK) ? *(const float2*)(xw + (size_t)r0 * 128 + k0) : make_float2(0.f, 0.f);
    float2 p1 = (r1 < NTOK) ? *(const float2*)(xw + (size_t)r1 * 128 + k0) : make_float2(0.f, 0.f);
    float2 p2 = (r0 < NTOK) ? *(const float2*)(xw + (size_t)r0 * 128 + k0 + 8) : make_float2(0.f, 0.f);
    float2 p3 = (r1 < NTOK) ? *(const float2*)(xw + (size_t)r1 * 128 + k0 + 8) : make_float2(0.f, 0.f);
    uint4 hi, lo;
    tsplit2(p0.x, p0.y, hi.x, lo.x);
    tsplit2(p1.x, p1.y, hi.y, lo.y);
    tsplit2(p2.x, p2.y, hi.z, lo.z);
    tsplit2(p3.x, p3.y, hi.w, lo.w);
    size_t base = (size_t)(blkw * 8 + kc) * 64;
    g_xfrag[base + lane] = hi;
    g_xfrag[base + 32 + lane] = lo;
}

// ===========================================================================
// HMMA GEMM (proj only): 64M x 128N, W frags from L2, packed A in, fp32 out.
// ===========================================================================
__global__ __launch_bounds__(256, 3) void gemm_proj(
    const uint32_t* __restrict__ Ain, const uint4* __restrict__ Wfrag,
    const float* __restrict__ bias, float* __restrict__ Cf)
{
    __shared__ char sm[32768];
    const uint32_t smb = smem_u32(sm);
    const int tid = threadIdx.x;
    const int wid = tid >> 5, lane = tid & 31;
    const size_t m0 = (size_t)blockIdx.x * 64;

#pragma unroll
    for (int i = 0; i < 8; i++) {
        int idx = tid + 256 * i;
        int r = idx >> 5;
        int c4 = (idx & 31) << 2;
        uint4 p = ((const uint4*)Ain)[(m0 + r) * 32 + (c4 >> 2)];
        uint2 hi, lo;
        hi.x = HIPAIR(p.x, p.y); hi.y = HIPAIR(p.z, p.w);
        lo.x = LOPAIR(p.x, p.y); lo.y = LOPAIR(p.z, p.w);
        *(uint2*)(sm + swz(r, c4 * 2)) = hi;
        *(uint2*)(sm + 16384 + swz(r, c4 * 2)) = lo;
    }
    __syncthreads();

    const int wm = (wid & 1) * 32;
    const int wnb = (wid >> 1) * 4;
    const int rq = lane >> 2, cq = (lane & 3) * 2;

    float acc[2][4][4];
#pragma unroll
    for (int mi = 0; mi < 2; mi++)
#pragma unroll
        for (int ni = 0; ni < 4; ni++)
#pragma unroll
            for (int c = 0; c < 4; c++) acc[mi][ni][c] = 0.f;

#pragma unroll
    for (int kc = 0; kc < 8; kc++) {
        uint32_t cb = (uint32_t)(kc * 32 + ((lane >> 4) & 1) * 16);
        uint32_t ah[2][4], al[2][4];
#pragma unroll
        for (int mi = 0; mi < 2; mi++) {
            uint32_t r = (uint32_t)(wm + mi * 16 + (lane & 15));
            ldsm_x4(ah[mi], smb + swz(r, cb));
            ldsm_x4(al[mi], smb + 16384 + swz(r, cb));
        }
        const uint4* wp = Wfrag + ((size_t)kc * 16 + wnb) * 32 + lane;
#pragma unroll
        for (int ni = 0; ni < 4; ni++) {
            uint4 w = wp[ni * 32];
            uint32_t B0[2] = {w.x, w.y};
            uint32_t Bl[2] = {w.z, w.w};
#pragma unroll
            for (int mi = 0; mi < 2; mi++) {
                mma_bf16(acc[mi][ni], ah[mi], B0);
                mma_bf16(acc[mi][ni], al[mi], B0);
                mma_bf16(acc[mi][ni], ah[mi], Bl);
            }
        }
    }

#pragma unroll
    for (int mi = 0; mi < 2; mi++) {
        size_t rA = m0 + wm + mi * 16 + rq;
        size_t rB = rA + 8;
#pragma unroll
        for (int ni = 0; ni < 4; ni++) {
            int col = wnb * 8 + ni * 8 + cq;
            float b0 = bias[col], b1 = bias[col + 1];
            *(float2*)(Cf + rA * 128 + col) =
                make_float2(acc[mi][ni][0] + b0, acc[mi][ni][1] + b1);
            *(float2*)(Cf + rB * 128 + col) =
                make_float2(acc[mi][ni][2] + b0, acc[mi][ni][3] + b1);
        }
    }
}

// ===========================================================================
// Fused QKV + attention: one CTA per (head, window), 224 threads (7 warps).
// Warp wid owns rows [16*wid, 16*wid+16). Phase 1: QKV gemm from x-frag image
// + W-frag image -> hi/lo smem tiles. Phase 2: S/softmax/PV as before.
// ===========================================================================
#define PITCH 80
#define QH_OFF 0
#define QL_OFF 10240
#define KH_OFF 20480
#define KL_OFF 29440
#define VH_OFF 38400
#define VL_OFF 47360
#define ATTN_SMEM 56320

__global__ __launch_bounds__(224, 3) void attn_fused_kernel() {
    extern __shared__ char smraw[];
    const uint32_t smb = smem_u32(smraw);
    char* sm = smraw;

    const int h = blockIdx.x, b = blockIdx.y;
    const int tid = threadIdx.x;
    const int wid = tid >> 5, lane = tid & 31;

    const int l8 = lane & 7;
    const int rq = lane >> 2;
    const int cq = (lane & 3) * 2;
    const int l4 = lane & 3;
    const int sel16 = (lane >> 4) & 1;

    // ================= Phase 1: QKV projection for this warp's 16 rows ======
    {
        float acc[12][4];
#pragma unroll
        for (int f = 0; f < 12; f++)
#pragma unroll
            for (int c = 0; c < 4; c++) acc[f][c] = 0.f;

        const uint4* xf = g_xfrag + (size_t)((b * 7 + wid) * 8) * 64 + lane;
#pragma unroll
        for (int kc = 0; kc < 8; kc++) {
            uint4 a4 = xf[kc * 64];
            uint4 l4v = xf[kc * 64 + 32];
            uint32_t ah[4] = {a4.x, a4.y, a4.z, a4.w};
            uint32_t al[4] = {l4v.x, l4v.y, l4v.z, l4v.w};
#pragma unroll
            for (int t = 0; t < 3; t++) {
                const uint4* wp = g_wfrag + ((size_t)(t * 8 + kc) * 16 + h * 4) * 32 + lane;
#pragma unroll
                for (int nb = 0; nb < 4; nb++) {
                    uint4 w = wp[nb * 32];
                    uint32_t B0[2] = {w.x, w.y};
                    uint32_t Bl[2] = {w.z, w.w};
                    mma_bf16(acc[t * 4 + nb], ah, B0);
                    mma_bf16(acc[t * 4 + nb], al, B0);
                    mma_bf16(acc[t * 4 + nb], ah, Bl);
                }
            }
        }

        // epilogue: +bias, split hi/lo, store to smem tiles
        const uint32_t hibase[3] = {QH_OFF, KH_OFF, VH_OFF};
        const uint32_t lobase[3] = {QL_OFF, KL_OFF, VL_OFF};
        uint32_t rowA = (uint32_t)(wid * 16 + rq);
#pragma unroll
        for (int t = 0; t < 3; t++) {
#pragma unroll
            for (int nb = 0; nb < 4; nb++) {
                int colp = nb * 8 + cq;
                float b0 = g_qkvb[t * 128 + h * 32 + colp];
                float b1 = g_qkvb[t * 128 + h * 32 + colp + 1];
                uint32_t hi, lo;
                tsplit2(acc[t * 4 + nb][0] + b0, acc[t * 4 + nb][1] + b1, hi, lo);
                uint32_t off = rowA * PITCH + (uint32_t)colp * 2;
                *(uint32_t*)(sm + hibase[t] + off) = hi;
                *(uint32_t*)(sm + lobase[t] + off) = lo;
                tsplit2(acc[t * 4 + nb][2] + b0, acc[t * 4 + nb][3] + b1, hi, lo);
                off += 8 * PITCH;
                *(uint32_t*)(sm + hibase[t] + off) = hi;
                *(uint32_t*)(sm + lobase[t] + off) = lo;
            }
        }
    }
    __syncthreads();

    // ================= Phase 2: attention ===================================
    // ---- S = QK^T: single kc loop, 3 products share fragments ----
    float acc[13][4];
#pragma unroll
    for (int nt = 0; nt < 13; nt++)
#pragma unroll
        for (int c = 0; c < 4; c++) acc[nt][c] = 0.f;

#pragma unroll
    for (int kc = 0; kc < 2; kc++) {
        uint32_t r = (uint32_t)(wid * 16 + (lane & 15));
        uint32_t aoff = (uint32_t)(kc * 32 + sel16 * 16);
        uint32_t qh[4], ql[4];
        ldsm_x4(qh, smb + QH_OFF + r * PITCH + aoff);
        ldsm_x4(ql, smb + QL_OFF + r * PITCH + aoff);
        uint32_t boff = (uint32_t)(kc * 32 + ((lane >> 3) & 1) * 16);
#pragma unroll
        for (int nt2 = 0; nt2 < 6; nt2++) {
            uint32_t row = (uint32_t)((2 * nt2 + sel16) * 8 + l8);
            uint32_t kh[4], kl[4];
            ldsm_x4(kh, smb + KH_OFF + row * PITCH + boff);
            ldsm_x4(kl, smb + KL_OFF + row * PITCH + boff);
            mma_bf16(acc[2 * nt2], qh, kh);
            mma_bf16(acc[2 * nt2], qh, kl);
            mma_bf16(acc[2 * nt2], ql, kh);
            mma_bf16(acc[2 * nt2 + 1], qh, kh + 2);
            mma_bf16(acc[2 * nt2 + 1], qh, kl + 2);
            mma_bf16(acc[2 * nt2 + 1], ql, kh + 2);
        }
        {
            uint32_t kh[2], kl[2];
            ldsm_x2(kh, smb + KH_OFF + (uint32_t)(96 + l8) * PITCH + boff);
            ldsm_x2(kl, smb + KL_OFF + (uint32_t)(96 + l8) * PITCH + boff);
            mma_bf16(acc[12], qh, kh);
            mma_bf16(acc[12], qh, kl);
            mma_bf16(acc[12], ql, kh);
        }
    }

    // ---- fused bias + exp2 + rowsum (branch-free, coalesced sbm) ----
    const uint32_t* sbm = g_sbm +
        ((size_t)((b & (NWIN - 1)) * HEADS + h)) * (13 * 512);
    const int rA = wid * 16 + rq;
    const int rB = rA + 8;
    const uint32_t sboffA = (uint32_t)(rA * 4 + l4);
    float sA = 0.f, sB = 0.f;
#pragma unroll
    for (int nt = 0; nt < 13; nt++) {
        uint32_t uA = __ldg(sbm + nt * 512 + sboffA);
        uint32_t uB = __ldg(sbm + nt * 512 + sboffA + 32);
        __nv_bfloat162 bA = *(__nv_bfloat162*)&uA;
        __nv_bfloat162 bB = *(__nv_bfloat162*)&uB;
        float e0 = ex2f(acc[nt][0] + __bfloat162float(bA.x));
        float e1 = ex2f(acc[nt][1] + __bfloat162float(bA.y));
        float e2 = ex2f(acc[nt][2] + __bfloat162float(bB.x));
        float e3 = ex2f(acc[nt][3] + __bfloat162float(bB.y));
        acc[nt][0] = e0; acc[nt][1] = e1;
        acc[nt][2] = e2; acc[nt][3] = e3;
        sA += e0 + e1; sB += e2 + e3;
    }
    sA += __shfl_xor_sync(0xffffffffu, sA, 1);
    sA += __shfl_xor_sync(0xffffffffu, sA, 2);
    sB += __shfl_xor_sync(0xffffffffu, sB, 1);
    sB += __shfl_xor_sync(0xffffffffu, sB, 2);

    // ---- O = P V: single kc loop, 3 products share V fragments ----
    float oacc[4][4];
#pragma unroll
    for (int nh = 0; nh < 4; nh++)
#pragma unroll
        for (int c = 0; c < 4; c++) oacc[nh][c] = 0.f;

#pragma unroll
    for (int kc = 0; kc < 7; kc++) {
        int nt0 = 2 * kc, nt1 = nt0 + 1;
        float w0 = 0.f, w1 = 0.f, w2 = 0.f, w3 = 0.f;
        if (nt1 < 13) {
            w0 = acc[nt1][0]; w1 = acc[nt1][1];
            w2 = acc[nt1][2]; w3 = acc[nt1][3];
        }
        uint32_t amh[4], aml[4];
        tsplit2(acc[nt0][0], acc[nt0][1], amh[0], aml[0]);
        tsplit2(acc[nt0][2], acc[nt0][3], amh[1], aml[1]);
        tsplit2(w0, w1, amh[2], aml[2]);
        tsplit2(w2, w3, amh[3], aml[3]);
        uint32_t vrow = (uint32_t)(kc * 16 + ((lane >> 3) & 1) * 8 + l8);
#pragma unroll
        for (int nh2 = 0; nh2 < 2; nh2++) {
            uint32_t coff = (uint32_t)((2 * nh2 + sel16) * 16);
            uint32_t vh[4], vl[4];
            ldsm_x4t(vh, smb + VH_OFF + vrow * PITCH + coff);
            ldsm_x4t(vl, smb + VL_OFF + vrow * PITCH + coff);
            mma_bf16(oacc[2 * nh2], amh, vh);
            mma_bf16(oacc[2 * nh2], amh, vl);
            mma_bf16(oacc[2 * nh2], aml, vh);
            mma_bf16(oacc[2 * nh2 + 1], amh, vh + 2);
            mma_bf16(oacc[2 * nh2 + 1], amh, vl + 2);
            mma_bf16(oacc[2 * nh2 + 1], aml, vh + 2);
        }
    }

    // ---- epilogue: normalize + pack ----
    float invA = 1.0f / sA;
    float invB = 1.0f / sB;
#pragma unroll
    for (int nh = 0; nh < 4; nh++) {
        int col = nh * 8 + cq;
        if (rA < 98) {
            *(uint2*)(g_att + ((size_t)b * NTOK + rA) * 128 + h * 32 + col) =
                make_uint2(pack_e(oacc[nh][0] * invA), pack_e(oacc[nh][1] * invA));
        }
        if (rB < 98) {
            *(uint2*)(g_att + ((size_t)b * NTOK + rB) * 128 + h * 32 + col) =
                make_uint2(pack_e(oacc[nh][2] * invB), pack_e(oacc[nh][3] * invB));
        }
    }
}

// ===========================================================================
extern "C" void kernel_launch(void* const* d_in, const int* in_sizes, int n_in,
                              void* d_out, int out_size) {
    const float* x          = (const float*)d_in[0];
    const float* mask       = (const float*)d_in[1];
    const float* qkv_w      = (const float*)d_in[2];
    const float* qkv_b      = (const float*)d_in[3];
    const float* proj_w     = (const float*)d_in[4];
    const float* proj_b     = (const float*)d_in[5];
    const float* bias_table = (const float*)d_in[6];
    const int*   rel_index  = (const int*)d_in[7];
    float* out = (float*)d_out;

    void *att_ptr, *wfp;
    cudaGetSymbolAddress(&att_ptr, g_att);
    cudaGetSymbolAddress(&wfp, g_wfrag);

    cudaFuncSetAttribute(attn_fused_kernel,
                         cudaFuncAttributeMaxDynamicSharedMemorySize, ATTN_SMEM);

    // 1. prep: bias+mask fragment table, W fragment image, x fragment image
    build_sbm_kernel<<<dim3(26, NWIN * HEADS), 256>>>(bias_table, rel_index, mask);
    split_w_kernel<<<64, 256>>>(qkv_w, proj_w, qkv_b);
    build_xfrag<<<(BATCH * 7 * 8 * 32 + 255) / 256, 256>>>(x);
    // 2. fused QKV + attention
    attn_fused_kernel<<<dim3(HEADS, BATCH), 224, ATTN_SMEM>>>();
    // 3. output projection
    gemm_proj<<<MTOT / 64, 256>>>(
        (const uint32_t*)att_ptr, (const uint4*)wfp + 12288, proj_b, out);
}